// round 7
// baseline (speedup 1.0000x reference)
#include <cuda_runtime.h>
#include <math.h>

#define BB  32
#define PP  24
#define HHN 24
#define EE  300
#define DD  512
#define GG  4096   // 8*D
#define HP  25     // H+1 (padded grid dim)

// Grid state with zero-padding at row 0 / col 0 (never written -> stays zero).
// Cell (i,j) stored at [(i+1)*HP + (j+1)].
__device__ float g_h[(PP+1)*HP][BB][DD];
__device__ float g_c[(PP+1)*HP][BB][DD];
// Hoisted input projections: A[i] = prem_emb[i] @ W_ih[:, :E].T + b_ih + b_hh
//                            Bh[j] = hyp_emb[j] @ W_ih[:, E:].T
__device__ float g_A[PP][BB][GG];
__device__ float g_Bh[HHN][BB][GG];
// Per-diagonal LSTM cell outputs (pre-condense), indexed by cell-on-diagonal.
__device__ float g_h2[HHN][BB][2*DD];
__device__ float g_c2[HHN][BB][2*DD];
// MLP intermediates
__device__ float g_m1[BB][DD];
__device__ float g_m2[BB][DD];

__device__ __forceinline__ float sigf(float x) { return 1.0f / (1.0f + expf(-x)); }

// Packed dual-FMA (sm_100+): d.lo += a.lo*b.lo ; d.hi += a.hi*b.hi
#define FFMA2(d, a, b) asm("fma.rn.f32x2 %0, %1, %2, %0;" : "+l"(d) : "l"(a), "l"(b))

__device__ __forceinline__ float f2lo(unsigned long long v) { return __uint_as_float((unsigned)v); }
__device__ __forceinline__ float f2hi(unsigned long long v) { return __uint_as_float((unsigned)(v >> 32)); }

// ---------------------------------------------------------------------------
// Prologue: gather embeddings + input GEMMs into g_A / g_Bh.
// grid = (24 seq, 32 n-chunks of 128, 2 [A|Bh]), block = 256
// ---------------------------------------------------------------------------
__global__ void __launch_bounds__(256) prologue_kernel(
    const int* __restrict__ premise, const int* __restrict__ hypothesis,
    const float* __restrict__ emb, const float* __restrict__ W_ih,
    const float* __restrict__ b_ih, const float* __restrict__ b_hh)
{
    int seq = blockIdx.x;
    int n0  = blockIdx.y * 128;
    bool isA = (blockIdx.z == 0);
    const int* sidx = isA ? premise : hypothesis;   // both [B,24] row-major
    int coff = isA ? 0 : EE;

    __shared__ float Xs[32][33];
    __shared__ float Ws[128][33];
    __shared__ int   rows[32];

    int tid = threadIdx.x;
    int tr = tid >> 5, tc = tid & 31;
    if (tid < 32) rows[tid] = sidx[tid * 24 + seq];
    __syncthreads();

    float acc[4][4];
#pragma unroll
    for (int a = 0; a < 4; a++)
#pragma unroll
        for (int b = 0; b < 4; b++) acc[a][b] = 0.f;

    for (int k0 = 0; k0 < 320; k0 += 32) {
        {
            int b = tid >> 3;
            int kq = (tid & 7) * 4;
            int k = k0 + kq;
            float4 v = make_float4(0.f, 0.f, 0.f, 0.f);
            if (k < EE) v = *(const float4*)(emb + (long)rows[b] * EE + k);
            Xs[b][kq] = v.x; Xs[b][kq + 1] = v.y; Xs[b][kq + 2] = v.z; Xs[b][kq + 3] = v.w;
        }
#pragma unroll
        for (int t = 0; t < 4; t++) {
            int idx = tid + t * 256;
            int n = idx >> 3;
            int kq = (idx & 7) * 4;
            int k = k0 + kq;
            float4 w = make_float4(0.f, 0.f, 0.f, 0.f);
            if (k < EE) w = *(const float4*)(W_ih + (long)(n0 + n) * (2 * EE) + coff + k);
            Ws[n][kq] = w.x; Ws[n][kq + 1] = w.y; Ws[n][kq + 2] = w.z; Ws[n][kq + 3] = w.w;
        }
        __syncthreads();
#pragma unroll
        for (int kk = 0; kk < 32; kk++) {
            float xv[4], wv[4];
#pragma unroll
            for (int rr = 0; rr < 4; rr++) xv[rr] = Xs[tr + 8 * rr][kk];
#pragma unroll
            for (int cc = 0; cc < 4; cc++) wv[cc] = Ws[cc * 32 + tc][kk];
#pragma unroll
            for (int rr = 0; rr < 4; rr++)
#pragma unroll
                for (int cc = 0; cc < 4; cc++)
                    acc[rr][cc] = fmaf(xv[rr], wv[cc], acc[rr][cc]);
        }
        __syncthreads();
    }

    float* dst = isA ? &g_A[seq][0][0] : &g_Bh[seq][0][0];
#pragma unroll
    for (int rr = 0; rr < 4; rr++) {
        int b = tr + 8 * rr;
#pragma unroll
        for (int cc = 0; cc < 4; cc++) {
            int n = n0 + cc * 32 + tc;
            float v = acc[rr][cc];
            if (isA) v += b_ih[n] + b_hh[n];
            dst[b * GG + n] = v;
        }
    }
}

// ---------------------------------------------------------------------------
// Gates kernel (per diagonal): recurrent GEMM + fused LSTM nonlinearity.
// grid = (ncells, 32 m-chunks of 32), block = 256
// Block computes 32 m-cols x 4 gates (128 output cols of the 4096), K = 1024.
// Column interleave: local col n -> gate g = n&3, m = m0 + (n>>2), so each
// thread owns all 4 gates of its m columns -> elementwise fully fused.
// f32x2 packed FFMA + register-prefetch pipeline + transposed smem tiles.
// ---------------------------------------------------------------------------
__global__ void __launch_bounds__(256) gates_kernel(
    const float* __restrict__ W_hh, int d, int i_lo)
{
    int ci = blockIdx.x;
    int i = i_lo + ci;
    int j = d - i;
    int m0 = blockIdx.y * 32;

    const float* leftH = &g_h[i * HP + (j + 1)][0][0];       // cell (i-1, j)
    const float* lowH  = &g_h[(i + 1) * HP + j][0][0];       // cell (i, j-1)
    const float* leftC = &g_c[i * HP + (j + 1)][0][0];
    const float* lowC  = &g_c[(i + 1) * HP + j][0][0];

    __shared__ float2 Xs[32][34];   // [kk][b], x duplicated in both halves
    __shared__ float  Ws[32][132];  // [kk][n], n = local col (gate-interleaved)

    int tid = threadIdx.x;
    int tr = tid >> 5, tc = tid & 31;   // tr: 4-row group, tc: m column

    // --- W load mapping: one row per thread, 4 k-offsets ---
    int n = tid & 127;                  // local col
    int g = n & 3, mm = n >> 2;
    long grow = (long)(g * 1024 + m0 + mm);
    const float* wrow = W_hh + grow * 1024;
    int kkbase = (tid >> 7) * 4;        // 0 or 4; slots add +8 each

    // --- X load mapping ---
    int xb = tid >> 3;
    int xkq = (tid & 7) * 4;
    const float* xptrL = leftH + xb * DD + xkq;        // for k0 < 512
    const float* xptrR = lowH  + xb * DD + xkq - 512;  // for k0 >= 512

    unsigned long long acc[4][2];
#pragma unroll
    for (int r = 0; r < 4; r++) { acc[r][0] = 0ull; acc[r][1] = 0ull; }

    float4 xreg;
    float4 wreg[4];
    // prefetch k0 = 0
    xreg = *(const float4*)(xptrL);
#pragma unroll
    for (int s = 0; s < 4; s++) wreg[s] = *(const float4*)(wrow + kkbase + 8 * s);

    for (int k0 = 0; k0 < 1024; k0 += 32) {
        __syncthreads();
        // store prefetched tile to smem
        Xs[xkq + 0][xb] = make_float2(xreg.x, xreg.x);
        Xs[xkq + 1][xb] = make_float2(xreg.y, xreg.y);
        Xs[xkq + 2][xb] = make_float2(xreg.z, xreg.z);
        Xs[xkq + 3][xb] = make_float2(xreg.w, xreg.w);
#pragma unroll
        for (int s = 0; s < 4; s++) {
            int kk = kkbase + 8 * s;
            Ws[kk + 0][n] = wreg[s].x; Ws[kk + 1][n] = wreg[s].y;
            Ws[kk + 2][n] = wreg[s].z; Ws[kk + 3][n] = wreg[s].w;
        }
        __syncthreads();
        // prefetch next tile
        if (k0 + 32 < 1024) {
            int kn = k0 + 32;
            const float* xp = (kn < 512) ? (xptrL + kn) : (xptrR + kn);
            xreg = *(const float4*)xp;
#pragma unroll
            for (int s = 0; s < 4; s++) wreg[s] = *(const float4*)(wrow + kn + kkbase + 8 * s);
        }
        // compute
#pragma unroll
        for (int kk = 0; kk < 32; kk++) {
            ulonglong2 x01 = *(const ulonglong2*)&Xs[kk][4 * tr];
            ulonglong2 x23 = *(const ulonglong2*)&Xs[kk][4 * tr + 2];
            ulonglong2 w   = *(const ulonglong2*)&Ws[kk][4 * tc];
            FFMA2(acc[0][0], x01.x, w.x); FFMA2(acc[0][1], x01.x, w.y);
            FFMA2(acc[1][0], x01.y, w.x); FFMA2(acc[1][1], x01.y, w.y);
            FFMA2(acc[2][0], x23.x, w.x); FFMA2(acc[2][1], x23.x, w.y);
            FFMA2(acc[3][0], x23.y, w.x); FFMA2(acc[3][1], x23.y, w.y);
        }
    }

    // Elementwise LSTM. Thread owns rows b = 4*tr+q, column m = m0 + tc,
    // gates packed as: acc[q][0] = (i, f), acc[q][1] = (g, o).
    int m = m0 + tc;
    const float* Ai = &g_A[i][0][0];
    const float* Bj = &g_Bh[j][0][0];
    float* h2o = &g_h2[ci][0][0];
    float* c2o = &g_c2[ci][0][0];
    const float* cPrev = (m < DD) ? (leftC + m) : (lowC + m - DD);
#pragma unroll
    for (int q = 0; q < 4; q++) {
        int b = 4 * tr + q;
        long ab = (long)b * GG + m;
        float gi = f2lo(acc[q][0]) + Ai[ab]        + Bj[ab];
        float gf = f2hi(acc[q][0]) + Ai[ab + 1024] + Bj[ab + 1024];
        float gg = f2lo(acc[q][1]) + Ai[ab + 2048] + Bj[ab + 2048];
        float go = f2hi(acc[q][1]) + Ai[ab + 3072] + Bj[ab + 3072];
        float cp = cPrev[b * DD];
        float c2 = sigf(gf) * cp + sigf(gi) * tanhf(gg);
        float h2 = sigf(go) * tanhf(c2);
        c2o[b * (2 * DD) + m] = c2;
        h2o[b * (2 * DD) + m] = h2;
    }
}

// ---------------------------------------------------------------------------
// Condense kernel (per diagonal): nh = h2 @ W_ch.T + b_ch ; nc = c2 @ W_cc.T + b_cc
// grid = (ncells, 8) : y>>2 selects h/c, y&3 selects 128-col chunk of 512.
// C[32 x 128], K = 1024. f32x2 + prefetch pipeline. Writes padded grid (i+1,j+1).
// ---------------------------------------------------------------------------
__global__ void __launch_bounds__(256) condense_kernel(
    const float* __restrict__ W_ch, const float* __restrict__ b_ch,
    const float* __restrict__ W_cc, const float* __restrict__ b_cc,
    int d, int i_lo)
{
    int ci = blockIdx.x;
    int i = i_lo + ci;
    int j = d - i;
    int which = blockIdx.y >> 2;            // 0 -> h path, 1 -> c path
    int n0 = (blockIdx.y & 3) * 128;

    const float* X    = which ? &g_c2[ci][0][0] : &g_h2[ci][0][0];
    const float* W    = which ? W_cc : W_ch;
    const float* bias = which ? b_cc : b_ch;
    float* out = which ? &g_c[(i + 1) * HP + (j + 1)][0][0]
                       : &g_h[(i + 1) * HP + (j + 1)][0][0];

    __shared__ float2 Xs[32][34];
    __shared__ float  Ws[32][132];

    int tid = threadIdx.x;
    int tr = tid >> 5, tc = tid & 31;

    int n = tid & 127;
    const float* wrow = W + (long)(n0 + n) * 1024;
    int kkbase = (tid >> 7) * 4;

    int xb = tid >> 3;
    int xkq = (tid & 7) * 4;
    const float* xptr = X + xb * (2 * DD) + xkq;

    unsigned long long acc[4][2];
#pragma unroll
    for (int r = 0; r < 4; r++) { acc[r][0] = 0ull; acc[r][1] = 0ull; }

    float4 xreg = *(const float4*)xptr;
    float4 wreg[4];
#pragma unroll
    for (int s = 0; s < 4; s++) wreg[s] = *(const float4*)(wrow + kkbase + 8 * s);

    for (int k0 = 0; k0 < 1024; k0 += 32) {
        __syncthreads();
        Xs[xkq + 0][xb] = make_float2(xreg.x, xreg.x);
        Xs[xkq + 1][xb] = make_float2(xreg.y, xreg.y);
        Xs[xkq + 2][xb] = make_float2(xreg.z, xreg.z);
        Xs[xkq + 3][xb] = make_float2(xreg.w, xreg.w);
#pragma unroll
        for (int s = 0; s < 4; s++) {
            int kk = kkbase + 8 * s;
            Ws[kk + 0][n] = wreg[s].x; Ws[kk + 1][n] = wreg[s].y;
            Ws[kk + 2][n] = wreg[s].z; Ws[kk + 3][n] = wreg[s].w;
        }
        __syncthreads();
        if (k0 + 32 < 1024) {
            int kn = k0 + 32;
            xreg = *(const float4*)(xptr + kn);
#pragma unroll
            for (int s = 0; s < 4; s++) wreg[s] = *(const float4*)(wrow + kn + kkbase + 8 * s);
        }
#pragma unroll
        for (int kk = 0; kk < 32; kk++) {
            ulonglong2 x01 = *(const ulonglong2*)&Xs[kk][4 * tr];
            ulonglong2 x23 = *(const ulonglong2*)&Xs[kk][4 * tr + 2];
            ulonglong2 w   = *(const ulonglong2*)&Ws[kk][4 * tc];
            FFMA2(acc[0][0], x01.x, w.x); FFMA2(acc[0][1], x01.x, w.y);
            FFMA2(acc[1][0], x01.y, w.x); FFMA2(acc[1][1], x01.y, w.y);
            FFMA2(acc[2][0], x23.x, w.x); FFMA2(acc[2][1], x23.x, w.y);
            FFMA2(acc[3][0], x23.y, w.x); FFMA2(acc[3][1], x23.y, w.y);
        }
    }

    // Output: rows b = 4*tr+q, cols n0 + 4*tc .. +3 (natural order).
    float4 bv = *(const float4*)(bias + n0 + 4 * tc);
#pragma unroll
    for (int q = 0; q < 4; q++) {
        int b = 4 * tr + q;
        float4 o;
        o.x = f2lo(acc[q][0]) + bv.x;
        o.y = f2hi(acc[q][0]) + bv.y;
        o.z = f2lo(acc[q][1]) + bv.z;
        o.w = f2hi(acc[q][1]) + bv.w;
        *(float4*)(out + b * DD + n0 + 4 * tc) = o;
    }
}

// ---------------------------------------------------------------------------
// MLP layer: out = relu(X @ W.T + b), C[32 x 512], K = 512. grid = 4 blocks.
// ---------------------------------------------------------------------------
__global__ void __launch_bounds__(256) mlp_kernel(
    const float* __restrict__ W, const float* __restrict__ bias, int stage)
{
    const float* X = (stage == 0) ? &g_h[PP * HP + HHN][0][0] : &g_m1[0][0];
    float* out = (stage == 0) ? &g_m1[0][0] : &g_m2[0][0];
    int n0 = blockIdx.x * 128;

    __shared__ float Xs[32][33];
    __shared__ float Ws[128][33];
    int tid = threadIdx.x;
    int tr = tid >> 5, tc = tid & 31;

    float acc[4][4];
#pragma unroll
    for (int a = 0; a < 4; a++)
#pragma unroll
        for (int b = 0; b < 4; b++) acc[a][b] = 0.f;

    for (int k0 = 0; k0 < DD; k0 += 32) {
        {
            int b = tid >> 3;
            int kq = (tid & 7) * 4;
            float4 v = *(const float4*)(X + b * DD + k0 + kq);
            Xs[b][kq] = v.x; Xs[b][kq + 1] = v.y; Xs[b][kq + 2] = v.z; Xs[b][kq + 3] = v.w;
        }
#pragma unroll
        for (int t = 0; t < 4; t++) {
            int idx = tid + t * 256;
            int n = idx >> 3;
            int kq = (idx & 7) * 4;
            float4 w = *(const float4*)(W + (long)(n0 + n) * DD + k0 + kq);
            Ws[n][kq] = w.x; Ws[n][kq + 1] = w.y; Ws[n][kq + 2] = w.z; Ws[n][kq + 3] = w.w;
        }
        __syncthreads();
#pragma unroll
        for (int kk = 0; kk < 32; kk++) {
            float xv[4], wv[4];
#pragma unroll
            for (int rr = 0; rr < 4; rr++) xv[rr] = Xs[tr + 8 * rr][kk];
#pragma unroll
            for (int cc = 0; cc < 4; cc++) wv[cc] = Ws[cc * 32 + tc][kk];
#pragma unroll
            for (int rr = 0; rr < 4; rr++)
#pragma unroll
                for (int cc = 0; cc < 4; cc++)
                    acc[rr][cc] = fmaf(xv[rr], wv[cc], acc[rr][cc]);
        }
        __syncthreads();
    }

#pragma unroll
    for (int rr = 0; rr < 4; rr++) {
        int b = tr + 8 * rr;
#pragma unroll
        for (int cc = 0; cc < 4; cc++) {
            int n = n0 + cc * 32 + tc;
            out[b * DD + n] = fmaxf(acc[rr][cc] + bias[n], 0.f);
        }
    }
}

// ---------------------------------------------------------------------------
// Final: logits = g_m2 @ W3.T + b3 ; softmax over 3 classes. out [32,3] f32.
// ---------------------------------------------------------------------------
__global__ void __launch_bounds__(128) final_kernel(
    const float* __restrict__ W3, const float* __restrict__ b3, float* __restrict__ out)
{
    __shared__ float logits[32][3];
    int t = threadIdx.x;
    if (t < 96) {
        int b = t / 3, c = t % 3;
        float s = b3[c];
        for (int k = 0; k < DD; k++) s += g_m2[b][k] * W3[c * DD + k];
        logits[b][c] = s;
    }
    __syncthreads();
    if (t < 96) {
        int b = t / 3, c = t % 3;
        float mx = fmaxf(logits[b][0], fmaxf(logits[b][1], logits[b][2]));
        float e0 = expf(logits[b][0] - mx);
        float e1 = expf(logits[b][1] - mx);
        float e2 = expf(logits[b][2] - mx);
        out[b * 3 + c] = expf(logits[b][c] - mx) / (e0 + e1 + e2);
    }
}

// ---------------------------------------------------------------------------
extern "C" void kernel_launch(void* const* d_in, const int* in_sizes, int n_in,
                              void* d_out, int out_size)
{
    const int*   premise    = (const int*)d_in[0];
    const int*   hypothesis = (const int*)d_in[1];
    const float* emb        = (const float*)d_in[2];
    const float* W_ih       = (const float*)d_in[3];
    const float* W_hh       = (const float*)d_in[4];
    const float* b_ih       = (const float*)d_in[5];
    const float* b_hh       = (const float*)d_in[6];
    const float* W_ch       = (const float*)d_in[7];
    const float* b_ch       = (const float*)d_in[8];
    const float* W_cc       = (const float*)d_in[9];
    const float* b_cc       = (const float*)d_in[10];
    const float* W1         = (const float*)d_in[11];
    const float* b1         = (const float*)d_in[12];
    const float* W2         = (const float*)d_in[13];
    const float* b2         = (const float*)d_in[14];
    const float* W3         = (const float*)d_in[15];
    const float* b3         = (const float*)d_in[16];
    float* out = (float*)d_out;

    prologue_kernel<<<dim3(24, 32, 2), 256>>>(premise, hypothesis, emb, W_ih, b_ih, b_hh);

    for (int d = 0; d <= PP + HHN - 2; d++) {
        int i_lo = d - (HHN - 1); if (i_lo < 0) i_lo = 0;
        int i_hi = d < (PP - 1) ? d : (PP - 1);
        int nc = i_hi - i_lo + 1;
        gates_kernel<<<dim3(nc, 32), 256>>>(W_hh, d, i_lo);
        condense_kernel<<<dim3(nc, 8), 256>>>(W_ch, b_ch, W_cc, b_cc, d, i_lo);
    }

    mlp_kernel<<<4, 256>>>(W1, b1, 0);
    mlp_kernel<<<4, 256>>>(W2, b2, 1);
    final_kernel<<<1, 128>>>(W3, b3, out);
}

// round 10
// speedup vs baseline: 1.0637x; 1.0637x over previous
#include <cuda_runtime.h>
#include <math.h>

#define BB  32
#define PP  24
#define HHN 24
#define EE  300
#define DD  512
#define GG  4096   // 8*D
#define DR  25     // diagonal buffer rows: row 0 = zero boundary, rows 1..24 = cells

// Rolling diagonal state buffers, parity-indexed. Row 0 is never written ->
// stays zero (module-load zero init) -> zero boundary, deterministic across
// graph replays. Cell i on diagonal d lives at g_dh[d&1][i+1].
__device__ float g_dh[2][DR][BB][DD];
__device__ float g_dc[2][DR][BB][DD];
// Hoisted input projections: A[i] = prem_emb[i] @ W_ih[:, :E].T + b_ih + b_hh
//                            Bh[j] = hyp_emb[j] @ W_ih[:, E:].T
__device__ float g_A[PP][BB][GG];
__device__ float g_Bh[HHN][BB][GG];
// Per-diagonal LSTM cell outputs (pre-condense), indexed by cell-on-diagonal.
__device__ float g_h2[HHN][BB][2*DD];
__device__ float g_c2[HHN][BB][2*DD];
// MLP intermediates
__device__ float g_m1[BB][DD];
__device__ float g_m2[BB][DD];

__device__ __forceinline__ float sigf(float x) { return 1.0f / (1.0f + expf(-x)); }

// Packed dual-FMA (sm_100+): d.lo += a.lo*b.lo ; d.hi += a.hi*b.hi
#define FFMA2(d, a, b) asm("fma.rn.f32x2 %0, %1, %2, %0;" : "+l"(d) : "l"(a), "l"(b))

__device__ __forceinline__ float f2lo(unsigned long long v) { return __uint_as_float((unsigned)v); }
__device__ __forceinline__ float f2hi(unsigned long long v) { return __uint_as_float((unsigned)(v >> 32)); }

// ---------------------------------------------------------------------------
// Prologue: gather embeddings + input GEMMs into g_A / g_Bh.
// grid = (24 seq, 32 n-chunks of 128, 2 [A|Bh]), block = 256
// ---------------------------------------------------------------------------
__global__ void __launch_bounds__(256) prologue_kernel(
    const int* __restrict__ premise, const int* __restrict__ hypothesis,
    const float* __restrict__ emb, const float* __restrict__ W_ih,
    const float* __restrict__ b_ih, const float* __restrict__ b_hh)
{
    int seq = blockIdx.x;
    int n0  = blockIdx.y * 128;
    bool isA = (blockIdx.z == 0);
    const int* sidx = isA ? premise : hypothesis;   // both [B,24] row-major
    int coff = isA ? 0 : EE;

    __shared__ float Xs[32][33];
    __shared__ float Ws[128][33];
    __shared__ int   rows[32];

    int tid = threadIdx.x;
    int tr = tid >> 5, tc = tid & 31;
    if (tid < 32) rows[tid] = sidx[tid * 24 + seq];
    __syncthreads();

    float acc[4][4];
#pragma unroll
    for (int a = 0; a < 4; a++)
#pragma unroll
        for (int b = 0; b < 4; b++) acc[a][b] = 0.f;

    for (int k0 = 0; k0 < 320; k0 += 32) {
        {
            int b = tid >> 3;
            int kq = (tid & 7) * 4;
            int k = k0 + kq;
            float4 v = make_float4(0.f, 0.f, 0.f, 0.f);
            if (k < EE) v = *(const float4*)(emb + (long)rows[b] * EE + k);
            Xs[b][kq] = v.x; Xs[b][kq + 1] = v.y; Xs[b][kq + 2] = v.z; Xs[b][kq + 3] = v.w;
        }
#pragma unroll
        for (int t = 0; t < 4; t++) {
            int idx = tid + t * 256;
            int n = idx >> 3;
            int kq = (idx & 7) * 4;
            int k = k0 + kq;
            float4 w = make_float4(0.f, 0.f, 0.f, 0.f);
            if (k < EE) w = *(const float4*)(W_ih + (long)(n0 + n) * (2 * EE) + coff + k);
            Ws[n][kq] = w.x; Ws[n][kq + 1] = w.y; Ws[n][kq + 2] = w.z; Ws[n][kq + 3] = w.w;
        }
        __syncthreads();
#pragma unroll
        for (int kk = 0; kk < 32; kk++) {
            float xv[4], wv[4];
#pragma unroll
            for (int rr = 0; rr < 4; rr++) xv[rr] = Xs[tr + 8 * rr][kk];
#pragma unroll
            for (int cc = 0; cc < 4; cc++) wv[cc] = Ws[cc * 32 + tc][kk];
#pragma unroll
            for (int rr = 0; rr < 4; rr++)
#pragma unroll
                for (int cc = 0; cc < 4; cc++)
                    acc[rr][cc] = fmaf(xv[rr], wv[cc], acc[rr][cc]);
        }
        __syncthreads();
    }

    float* dst = isA ? &g_A[seq][0][0] : &g_Bh[seq][0][0];
#pragma unroll
    for (int rr = 0; rr < 4; rr++) {
        int b = tr + 8 * rr;
#pragma unroll
        for (int cc = 0; cc < 4; cc++) {
            int n = n0 + cc * 32 + tc;
            float v = acc[rr][cc];
            if (isA) v += b_ih[n] + b_hh[n];
            dst[b * GG + n] = v;
        }
    }
}

// ---------------------------------------------------------------------------
// Gates kernel (per diagonal): recurrent GEMM + fused LSTM nonlinearity.
// grid = (ncells, 32 m-chunks of 32), block = 256
// Block computes 32 m-cols x 4 gates (128 output cols of the 4096), K = 1024.
// Column interleave: local col n -> gate g = n&3, m = m0 + (n>>2), so each
// thread owns all 4 gates of its m columns -> elementwise fully fused.
// Neighbors come from the PREVIOUS diagonal's rolling buffer:
//   left (i-1,j) -> prev row i   (i==0 -> row 0 = zeros)
//   lower (i,j-1)-> prev row i+1 (j==0 -> row 0 = zeros)
// ---------------------------------------------------------------------------
__global__ void __launch_bounds__(256) gates_kernel(
    const float* __restrict__ W_hh, int d, int i_lo, int parity)
{
    int ci = blockIdx.x;
    int i = i_lo + ci;
    int j = d - i;
    int m0 = blockIdx.y * 32;
    int prev = parity ^ 1;

    int lowRow = (j == 0) ? 0 : (i + 1);
    const float* leftH = &g_dh[prev][i][0][0];
    const float* lowH  = &g_dh[prev][lowRow][0][0];
    const float* leftC = &g_dc[prev][i][0][0];
    const float* lowC  = &g_dc[prev][lowRow][0][0];

    __shared__ float2 Xs[32][34];   // [kk][b], x duplicated in both halves
    __shared__ float  Ws[32][132];  // [kk][n], n = local col (gate-interleaved)

    int tid = threadIdx.x;
    int tr = tid >> 5, tc = tid & 31;   // tr: 4-row group, tc: m column

    // --- W load mapping: one row per thread, 4 k-offsets ---
    int n = tid & 127;                  // local col
    int g = n & 3, mm = n >> 2;
    long grow = (long)(g * 1024 + m0 + mm);
    const float* wrow = W_hh + grow * 1024;
    int kkbase = (tid >> 7) * 4;        // 0 or 4; slots add +8 each

    // --- X load mapping ---
    int xb = tid >> 3;
    int xkq = (tid & 7) * 4;
    const float* xptrL = leftH + xb * DD + xkq;        // for k0 < 512
    const float* xptrR = lowH  + xb * DD + xkq - 512;  // for k0 >= 512

    unsigned long long acc[4][2];
#pragma unroll
    for (int r = 0; r < 4; r++) { acc[r][0] = 0ull; acc[r][1] = 0ull; }

    float4 xreg;
    float4 wreg[4];
    // prefetch k0 = 0
    xreg = *(const float4*)(xptrL);
#pragma unroll
    for (int s = 0; s < 4; s++) wreg[s] = *(const float4*)(wrow + kkbase + 8 * s);

    for (int k0 = 0; k0 < 1024; k0 += 32) {
        __syncthreads();
        // store prefetched tile to smem
        Xs[xkq + 0][xb] = make_float2(xreg.x, xreg.x);
        Xs[xkq + 1][xb] = make_float2(xreg.y, xreg.y);
        Xs[xkq + 2][xb] = make_float2(xreg.z, xreg.z);
        Xs[xkq + 3][xb] = make_float2(xreg.w, xreg.w);
#pragma unroll
        for (int s = 0; s < 4; s++) {
            int kk = kkbase + 8 * s;
            Ws[kk + 0][n] = wreg[s].x; Ws[kk + 1][n] = wreg[s].y;
            Ws[kk + 2][n] = wreg[s].z; Ws[kk + 3][n] = wreg[s].w;
        }
        __syncthreads();
        // prefetch next tile
        if (k0 + 32 < 1024) {
            int kn = k0 + 32;
            const float* xp = (kn < 512) ? (xptrL + kn) : (xptrR + kn);
            xreg = *(const float4*)xp;
#pragma unroll
            for (int s = 0; s < 4; s++) wreg[s] = *(const float4*)(wrow + kn + kkbase + 8 * s);
        }
        // compute
#pragma unroll
        for (int kk = 0; kk < 32; kk++) {
            ulonglong2 x01 = *(const ulonglong2*)&Xs[kk][4 * tr];
            ulonglong2 x23 = *(const ulonglong2*)&Xs[kk][4 * tr + 2];
            ulonglong2 w   = *(const ulonglong2*)&Ws[kk][4 * tc];
            FFMA2(acc[0][0], x01.x, w.x); FFMA2(acc[0][1], x01.x, w.y);
            FFMA2(acc[1][0], x01.y, w.x); FFMA2(acc[1][1], x01.y, w.y);
            FFMA2(acc[2][0], x23.x, w.x); FFMA2(acc[2][1], x23.x, w.y);
            FFMA2(acc[3][0], x23.y, w.x); FFMA2(acc[3][1], x23.y, w.y);
        }
    }

    // Elementwise LSTM. Thread owns rows b = 4*tr+q, column m = m0 + tc,
    // gates packed as: acc[q][0] = (i, f), acc[q][1] = (g, o).
    int m = m0 + tc;
    const float* Ai = &g_A[i][0][0];
    const float* Bj = &g_Bh[j][0][0];
    float* h2o = &g_h2[ci][0][0];
    float* c2o = &g_c2[ci][0][0];
    const float* cPrev = (m < DD) ? (leftC + m) : (lowC + m - DD);
#pragma unroll
    for (int q = 0; q < 4; q++) {
        int b = 4 * tr + q;
        long ab = (long)b * GG + m;
        float gi = f2lo(acc[q][0]) + Ai[ab]        + Bj[ab];
        float gf = f2hi(acc[q][0]) + Ai[ab + 1024] + Bj[ab + 1024];
        float gg = f2lo(acc[q][1]) + Ai[ab + 2048] + Bj[ab + 2048];
        float go = f2hi(acc[q][1]) + Ai[ab + 3072] + Bj[ab + 3072];
        float cp = cPrev[b * DD];
        float c2 = sigf(gf) * cp + sigf(gi) * tanhf(gg);
        float h2 = sigf(go) * tanhf(c2);
        c2o[b * (2 * DD) + m] = c2;
        h2o[b * (2 * DD) + m] = h2;
    }
}

// ---------------------------------------------------------------------------
// Condense kernel (per diagonal): nh = h2 @ W_ch.T + b_ch ; nc = c2 @ W_cc.T + b_cc
// grid = (ncells, 8) : y>>2 selects h/c, y&3 selects 128-col chunk of 512.
// C[32 x 128], K = 1024. Writes current diagonal buffer row i+1.
// ---------------------------------------------------------------------------
__global__ void __launch_bounds__(256) condense_kernel(
    const float* __restrict__ W_ch, const float* __restrict__ b_ch,
    const float* __restrict__ W_cc, const float* __restrict__ b_cc,
    int d, int i_lo, int parity)
{
    int ci = blockIdx.x;
    int i = i_lo + ci;
    int which = blockIdx.y >> 2;            // 0 -> h path, 1 -> c path
    int n0 = (blockIdx.y & 3) * 128;

    const float* X    = which ? &g_c2[ci][0][0] : &g_h2[ci][0][0];
    const float* W    = which ? W_cc : W_ch;
    const float* bias = which ? b_cc : b_ch;
    float* out = which ? &g_dc[parity][i + 1][0][0]
                       : &g_dh[parity][i + 1][0][0];

    __shared__ float2 Xs[32][34];
    __shared__ float  Ws[32][132];

    int tid = threadIdx.x;
    int tr = tid >> 5, tc = tid & 31;

    int n = tid & 127;
    const float* wrow = W + (long)(n0 + n) * 1024;
    int kkbase = (tid >> 7) * 4;

    int xb = tid >> 3;
    int xkq = (tid & 7) * 4;
    const float* xptr = X + xb * (2 * DD) + xkq;

    unsigned long long acc[4][2];
#pragma unroll
    for (int r = 0; r < 4; r++) { acc[r][0] = 0ull; acc[r][1] = 0ull; }

    float4 xreg = *(const float4*)xptr;
    float4 wreg[4];
#pragma unroll
    for (int s = 0; s < 4; s++) wreg[s] = *(const float4*)(wrow + kkbase + 8 * s);

    for (int k0 = 0; k0 < 1024; k0 += 32) {
        __syncthreads();
        Xs[xkq + 0][xb] = make_float2(xreg.x, xreg.x);
        Xs[xkq + 1][xb] = make_float2(xreg.y, xreg.y);
        Xs[xkq + 2][xb] = make_float2(xreg.z, xreg.z);
        Xs[xkq + 3][xb] = make_float2(xreg.w, xreg.w);
#pragma unroll
        for (int s = 0; s < 4; s++) {
            int kk = kkbase + 8 * s;
            Ws[kk + 0][n] = wreg[s].x; Ws[kk + 1][n] = wreg[s].y;
            Ws[kk + 2][n] = wreg[s].z; Ws[kk + 3][n] = wreg[s].w;
        }
        __syncthreads();
        if (k0 + 32 < 1024) {
            int kn = k0 + 32;
            xreg = *(const float4*)(xptr + kn);
#pragma unroll
            for (int s = 0; s < 4; s++) wreg[s] = *(const float4*)(wrow + kn + kkbase + 8 * s);
        }
#pragma unroll
        for (int kk = 0; kk < 32; kk++) {
            ulonglong2 x01 = *(const ulonglong2*)&Xs[kk][4 * tr];
            ulonglong2 x23 = *(const ulonglong2*)&Xs[kk][4 * tr + 2];
            ulonglong2 w   = *(const ulonglong2*)&Ws[kk][4 * tc];
            FFMA2(acc[0][0], x01.x, w.x); FFMA2(acc[0][1], x01.x, w.y);
            FFMA2(acc[1][0], x01.y, w.x); FFMA2(acc[1][1], x01.y, w.y);
            FFMA2(acc[2][0], x23.x, w.x); FFMA2(acc[2][1], x23.x, w.y);
            FFMA2(acc[3][0], x23.y, w.x); FFMA2(acc[3][1], x23.y, w.y);
        }
    }

    // Output: rows b = 4*tr+q, cols n0 + 4*tc .. +3 (natural order).
    float4 bv = *(const float4*)(bias + n0 + 4 * tc);
#pragma unroll
    for (int q = 0; q < 4; q++) {
        int b = 4 * tr + q;
        float4 o;
        o.x = f2lo(acc[q][0]) + bv.x;
        o.y = f2hi(acc[q][0]) + bv.y;
        o.z = f2lo(acc[q][1]) + bv.z;
        o.w = f2hi(acc[q][1]) + bv.w;
        *(float4*)(out + b * DD + n0 + 4 * tc) = o;
    }
}

// ---------------------------------------------------------------------------
// MLP layer: out = relu(X @ W.T + b), C[32 x 512], K = 512. grid = 4 blocks.
// ---------------------------------------------------------------------------
__global__ void __launch_bounds__(256) mlp_kernel(
    const float* __restrict__ W, const float* __restrict__ bias, int stage)
{
    // Final grid cell (23,23) is on diagonal 46 (parity 0), buffer row 24.
    const float* X = (stage == 0) ? &g_dh[0][24][0][0] : &g_m1[0][0];
    float* out = (stage == 0) ? &g_m1[0][0] : &g_m2[0][0];
    int n0 = blockIdx.x * 128;

    __shared__ float Xs[32][33];
    __shared__ float Ws[128][33];
    int tid = threadIdx.x;
    int tr = tid >> 5, tc = tid & 31;

    float acc[4][4];
#pragma unroll
    for (int a = 0; a < 4; a++)
#pragma unroll
        for (int b = 0; b < 4; b++) acc[a][b] = 0.f;

    for (int k0 = 0; k0 < DD; k0 += 32) {
        {
            int b = tid >> 3;
            int kq = (tid & 7) * 4;
            float4 v = *(const float4*)(X + b * DD + k0 + kq);
            Xs[b][kq] = v.x; Xs[b][kq + 1] = v.y; Xs[b][kq + 2] = v.z; Xs[b][kq + 3] = v.w;
        }
#pragma unroll
        for (int t = 0; t < 4; t++) {
            int idx = tid + t * 256;
            int n = idx >> 3;
            int kq = (idx & 7) * 4;
            float4 w = *(const float4*)(W + (long)(n0 + n) * DD + k0 + kq);
            Ws[n][kq] = w.x; Ws[n][kq + 1] = w.y; Ws[n][kq + 2] = w.z; Ws[n][kq + 3] = w.w;
        }
        __syncthreads();
#pragma unroll
        for (int kk = 0; kk < 32; kk++) {
            float xv[4], wv[4];
#pragma unroll
            for (int rr = 0; rr < 4; rr++) xv[rr] = Xs[tr + 8 * rr][kk];
#pragma unroll
            for (int cc = 0; cc < 4; cc++) wv[cc] = Ws[cc * 32 + tc][kk];
#pragma unroll
            for (int rr = 0; rr < 4; rr++)
#pragma unroll
                for (int cc = 0; cc < 4; cc++)
                    acc[rr][cc] = fmaf(xv[rr], wv[cc], acc[rr][cc]);
        }
        __syncthreads();
    }

#pragma unroll
    for (int rr = 0; rr < 4; rr++) {
        int b = tr + 8 * rr;
#pragma unroll
        for (int cc = 0; cc < 4; cc++) {
            int n = n0 + cc * 32 + tc;
            out[b * DD + n] = fmaxf(acc[rr][cc] + bias[n], 0.f);
        }
    }
}

// ---------------------------------------------------------------------------
// Final: logits = g_m2 @ W3.T + b3 ; softmax over 3 classes. out [32,3] f32.
// ---------------------------------------------------------------------------
__global__ void __launch_bounds__(128) final_kernel(
    const float* __restrict__ W3, const float* __restrict__ b3, float* __restrict__ out)
{
    __shared__ float logits[32][3];
    int t = threadIdx.x;
    if (t < 96) {
        int b = t / 3, c = t % 3;
        float s = b3[c];
        for (int k = 0; k < DD; k++) s += g_m2[b][k] * W3[c * DD + k];
        logits[b][c] = s;
    }
    __syncthreads();
    if (t < 96) {
        int b = t / 3, c = t % 3;
        float mx = fmaxf(logits[b][0], fmaxf(logits[b][1], logits[b][2]));
        float e0 = expf(logits[b][0] - mx);
        float e1 = expf(logits[b][1] - mx);
        float e2 = expf(logits[b][2] - mx);
        out[b * 3 + c] = expf(logits[b][c] - mx) / (e0 + e1 + e2);
    }
}

// ---------------------------------------------------------------------------
extern "C" void kernel_launch(void* const* d_in, const int* in_sizes, int n_in,
                              void* d_out, int out_size)
{
    const int*   premise    = (const int*)d_in[0];
    const int*   hypothesis = (const int*)d_in[1];
    const float* emb        = (const float*)d_in[2];
    const float* W_ih       = (const float*)d_in[3];
    const float* W_hh       = (const float*)d_in[4];
    const float* b_ih       = (const float*)d_in[5];
    const float* b_hh       = (const float*)d_in[6];
    const float* W_ch       = (const float*)d_in[7];
    const float* b_ch       = (const float*)d_in[8];
    const float* W_cc       = (const float*)d_in[9];
    const float* b_cc       = (const float*)d_in[10];
    const float* W1         = (const float*)d_in[11];
    const float* b1         = (const float*)d_in[12];
    const float* W2         = (const float*)d_in[13];
    const float* b2         = (const float*)d_in[14];
    const float* W3         = (const float*)d_in[15];
    const float* b3         = (const float*)d_in[16];
    float* out = (float*)d_out;

    prologue_kernel<<<dim3(24, 32, 2), 256>>>(premise, hypothesis, emb, W_ih, b_ih, b_hh);

    for (int d = 0; d <= PP + HHN - 2; d++) {
        int i_lo = d - (HHN - 1); if (i_lo < 0) i_lo = 0;
        int i_hi = d < (PP - 1) ? d : (PP - 1);
        int nc = i_hi - i_lo + 1;
        int parity = d & 1;
        gates_kernel<<<dim3(nc, 32), 256>>>(W_hh, d, i_lo, parity);
        condense_kernel<<<dim3(nc, 8), 256>>>(W_ch, b_ch, W_cc, b_cc, d, i_lo, parity);
    }

    mlp_kernel<<<4, 256>>>(W1, b1, 0);
    mlp_kernel<<<4, 256>>>(W2, b2, 1);
    final_kernel<<<1, 128>>>(W3, b3, out);
}

// round 11
// speedup vs baseline: 1.7385x; 1.6343x over previous
#include <cuda_runtime.h>
#include <math.h>

#define BB  32
#define PP  24
#define HHN 24
#define EE  300
#define DD  512
#define GG  4096   // 8*D
#define DR  25     // diagonal buffer rows: row 0 = zero boundary, rows 1..24 = cells

// Rolling diagonal state buffers, parity-indexed. Row 0 is never written ->
// stays zero -> zero boundary, deterministic across graph replays.
__device__ float g_dh[2][DR][BB][DD];
__device__ float g_dc[2][DR][BB][DD];
// Hoisted input projections: A[i] = prem_emb[i] @ W_ih[:, :E].T + b_ih + b_hh
//                            Bh[j] = hyp_emb[j] @ W_ih[:, E:].T
__device__ float g_A[PP][BB][GG];
__device__ float g_Bh[HHN][BB][GG];
// Per-diagonal LSTM cell outputs (pre-condense), indexed by cell-on-diagonal.
__device__ float g_h2[HHN][BB][2*DD];
__device__ float g_c2[HHN][BB][2*DD];
// MLP intermediates
__device__ float g_m1[BB][DD];
__device__ float g_m2[BB][DD];

__device__ __forceinline__ float sigf(float x) { return 1.0f / (1.0f + expf(-x)); }

// Packed dual-FMA (sm_100+): d.lo += a.lo*b.lo ; d.hi += a.hi*b.hi
#define FFMA2(d, a, b) asm("fma.rn.f32x2 %0, %1, %2, %0;" : "+l"(d) : "l"(a), "l"(b))

__device__ __forceinline__ float f2sum(unsigned long long v) {
    return __uint_as_float((unsigned)v) + __uint_as_float((unsigned)(v >> 32));
}

// ---------------------------------------------------------------------------
// Prologue: gather embeddings + input GEMMs into g_A / g_Bh.
// grid = (24 seq, 32 n-chunks of 128, 2 [A|Bh]), block = 256
// ---------------------------------------------------------------------------
__global__ void __launch_bounds__(256) prologue_kernel(
    const int* __restrict__ premise, const int* __restrict__ hypothesis,
    const float* __restrict__ emb, const float* __restrict__ W_ih,
    const float* __restrict__ b_ih, const float* __restrict__ b_hh)
{
    int seq = blockIdx.x;
    int n0  = blockIdx.y * 128;
    bool isA = (blockIdx.z == 0);
    const int* sidx = isA ? premise : hypothesis;   // both [B,24] row-major
    int coff = isA ? 0 : EE;

    __shared__ float Xs[32][33];
    __shared__ float Ws[128][33];
    __shared__ int   rows[32];

    int tid = threadIdx.x;
    int tr = tid >> 5, tc = tid & 31;
    if (tid < 32) rows[tid] = sidx[tid * 24 + seq];
    __syncthreads();

    float acc[4][4];
#pragma unroll
    for (int a = 0; a < 4; a++)
#pragma unroll
        for (int b = 0; b < 4; b++) acc[a][b] = 0.f;

    for (int k0 = 0; k0 < 320; k0 += 32) {
        {
            int b = tid >> 3;
            int kq = (tid & 7) * 4;
            int k = k0 + kq;
            float4 v = make_float4(0.f, 0.f, 0.f, 0.f);
            if (k < EE) v = *(const float4*)(emb + (long)rows[b] * EE + k);
            Xs[b][kq] = v.x; Xs[b][kq + 1] = v.y; Xs[b][kq + 2] = v.z; Xs[b][kq + 3] = v.w;
        }
#pragma unroll
        for (int t = 0; t < 4; t++) {
            int idx = tid + t * 256;
            int n = idx >> 3;
            int kq = (idx & 7) * 4;
            int k = k0 + kq;
            float4 w = make_float4(0.f, 0.f, 0.f, 0.f);
            if (k < EE) w = *(const float4*)(W_ih + (long)(n0 + n) * (2 * EE) + coff + k);
            Ws[n][kq] = w.x; Ws[n][kq + 1] = w.y; Ws[n][kq + 2] = w.z; Ws[n][kq + 3] = w.w;
        }
        __syncthreads();
#pragma unroll
        for (int kk = 0; kk < 32; kk++) {
            float xv[4], wv[4];
#pragma unroll
            for (int rr = 0; rr < 4; rr++) xv[rr] = Xs[tr + 8 * rr][kk];
#pragma unroll
            for (int cc = 0; cc < 4; cc++) wv[cc] = Ws[cc * 32 + tc][kk];
#pragma unroll
            for (int rr = 0; rr < 4; rr++)
#pragma unroll
                for (int cc = 0; cc < 4; cc++)
                    acc[rr][cc] = fmaf(xv[rr], wv[cc], acc[rr][cc]);
        }
        __syncthreads();
    }

    float* dst = isA ? &g_A[seq][0][0] : &g_Bh[seq][0][0];
#pragma unroll
    for (int rr = 0; rr < 4; rr++) {
        int b = tr + 8 * rr;
#pragma unroll
        for (int cc = 0; cc < 4; cc++) {
            int n = n0 + cc * 32 + tc;
            float v = acc[rr][cc];
            if (isA) v += b_ih[n] + b_hh[n];
            dst[b * GG + n] = v;
        }
    }
}

// ---------------------------------------------------------------------------
// Gates kernel (per diagonal): recurrent GEMM + fused LSTM nonlinearity.
// grid = (ncells, 32 m-chunks of 32), block = 256 (8 warps)
// Block tile: C[32 x 128], K = 1024. Local col n = 32*gate + mloc, so lane tc
// owns cols {tc, tc+32, tc+64, tc+96} = all 4 gates of m = m0+tc.
// FFMA2 packed along K (horizontal lo+hi sum at the end) -> natural k-major
// layouts, coalesced W loads (8 thr/row), XOR-swizzled 16B-chunk W smem
// (conflict-free stores AND loads), broadcast X reads. Reg-prefetch pipeline.
// ---------------------------------------------------------------------------
__global__ void __launch_bounds__(256) gates_kernel(
    const float* __restrict__ W_hh, int d, int i_lo, int parity)
{
    int ci = blockIdx.x;
    int i = i_lo + ci;
    int j = d - i;
    int m0 = blockIdx.y * 32;
    int prev = parity ^ 1;

    int lowRow = (j == 0) ? 0 : (i + 1);
    const float* leftH = &g_dh[prev][i][0][0];
    const float* lowH  = &g_dh[prev][lowRow][0][0];
    const float* leftC = &g_dc[prev][i][0][0];
    const float* lowC  = &g_dc[prev][lowRow][0][0];

    __shared__ float Xs[32][32];          // [b][kk] natural
    __shared__ float Ws2[8][128][4];      // [kqi][n ^ kqi][4] 16B chunks

    int tid = threadIdx.x;
    int w = tid >> 5, tc = tid & 31;

    // --- W loader: thread covers rows n = (tid>>3)+32t at k-offset kqi_w*4 ---
    int kqi_w = tid & 7;
    const float* wp[4];
    float* wsdst[4];
#pragma unroll
    for (int t = 0; t < 4; t++) {
        int n = (tid >> 3) + 32 * t;
        int grow = (n >> 5) * 1024 + m0 + (n & 31);     // gate*1024 + m
        wp[t] = W_hh + (long)grow * 1024 + kqi_w * 4;
        wsdst[t] = &Ws2[kqi_w][n ^ kqi_w][0];
    }

    // --- X loader ---
    int xb = tid >> 3;
    int xkq = (tid & 7) * 4;
    const float* xptrL = leftH + xb * DD + xkq;        // for k < 512
    const float* xptrR = lowH  + xb * DD + xkq - 512;  // for k >= 512

    unsigned long long acc[4][4];   // [row q][gate c], packed (even-k, odd-k)
#pragma unroll
    for (int q = 0; q < 4; q++)
#pragma unroll
        for (int c = 0; c < 4; c++) acc[q][c] = 0ull;

    float4 xreg = *(const float4*)xptrL;
    float4 wreg[4];
#pragma unroll
    for (int t = 0; t < 4; t++) wreg[t] = *(const float4*)wp[t];

    for (int k0 = 0; k0 < 1024; k0 += 32) {
        __syncthreads();
        *(float4*)&Xs[xb][xkq] = xreg;
#pragma unroll
        for (int t = 0; t < 4; t++) *(float4*)wsdst[t] = wreg[t];
        __syncthreads();
        if (k0 + 32 < 1024) {
            int kn = k0 + 32;
            xreg = *(const float4*)((kn < 512 ? xptrL : xptrR) + kn);
#pragma unroll
            for (int t = 0; t < 4; t++) wreg[t] = *(const float4*)(wp[t] + kn);
        }
#pragma unroll
        for (int kqi = 0; kqi < 8; kqi++) {
            ulonglong2 xv[4];
#pragma unroll
            for (int q = 0; q < 4; q++)
                xv[q] = *(const ulonglong2*)&Xs[4 * w + q][kqi * 4];
#pragma unroll
            for (int c = 0; c < 4; c++) {
                ulonglong2 wv = *(const ulonglong2*)&Ws2[kqi][(tc + 32 * c) ^ kqi][0];
                FFMA2(acc[0][c], xv[0].x, wv.x); FFMA2(acc[0][c], xv[0].y, wv.y);
                FFMA2(acc[1][c], xv[1].x, wv.x); FFMA2(acc[1][c], xv[1].y, wv.y);
                FFMA2(acc[2][c], xv[2].x, wv.x); FFMA2(acc[2][c], xv[2].y, wv.y);
                FFMA2(acc[3][c], xv[3].x, wv.x); FFMA2(acc[3][c], xv[3].y, wv.y);
            }
        }
    }

    // Elementwise LSTM. Thread: rows b = 4w+q, m = m0+tc, gates c = i,f,g,o.
    int m = m0 + tc;
    const float* Ai = &g_A[i][0][0];
    const float* Bj = &g_Bh[j][0][0];
    float* h2o = &g_h2[ci][0][0];
    float* c2o = &g_c2[ci][0][0];
    const float* cPrev = (m < DD) ? (leftC + m) : (lowC + m - DD);
#pragma unroll
    for (int q = 0; q < 4; q++) {
        int b = 4 * w + q;
        long ab = (long)b * GG + m;
        float gi = f2sum(acc[q][0]) + Ai[ab]        + Bj[ab];
        float gf = f2sum(acc[q][1]) + Ai[ab + 1024] + Bj[ab + 1024];
        float gg = f2sum(acc[q][2]) + Ai[ab + 2048] + Bj[ab + 2048];
        float go = f2sum(acc[q][3]) + Ai[ab + 3072] + Bj[ab + 3072];
        float cp = cPrev[b * DD];
        float c2 = sigf(gf) * cp + sigf(gi) * tanhf(gg);
        float h2 = sigf(go) * tanhf(c2);
        c2o[b * (2 * DD) + m] = c2;
        h2o[b * (2 * DD) + m] = h2;
    }
}

// ---------------------------------------------------------------------------
// Condense kernel (per diagonal): nh = h2 @ W_ch.T + b_ch ; nc = c2 @ W_cc.T + b_cc
// grid = (ncells, 8) : y>>2 selects h/c, y&3 selects 128-col chunk of 512.
// C[32 x 128], K = 1024. Same k-packed FFMA2 / swizzled-smem core.
// ---------------------------------------------------------------------------
__global__ void __launch_bounds__(256) condense_kernel(
    const float* __restrict__ W_ch, const float* __restrict__ b_ch,
    const float* __restrict__ W_cc, const float* __restrict__ b_cc,
    int d, int i_lo, int parity)
{
    int ci = blockIdx.x;
    int i = i_lo + ci;
    int which = blockIdx.y >> 2;            // 0 -> h path, 1 -> c path
    int n0 = (blockIdx.y & 3) * 128;

    const float* X    = which ? &g_c2[ci][0][0] : &g_h2[ci][0][0];
    const float* W    = which ? W_cc : W_ch;
    const float* bias = which ? b_cc : b_ch;
    float* out = which ? &g_dc[parity][i + 1][0][0]
                       : &g_dh[parity][i + 1][0][0];

    __shared__ float Xs[32][32];
    __shared__ float Ws2[8][128][4];

    int tid = threadIdx.x;
    int w = tid >> 5, tc = tid & 31;

    int kqi_w = tid & 7;
    const float* wp[4];
    float* wsdst[4];
#pragma unroll
    for (int t = 0; t < 4; t++) {
        int n = (tid >> 3) + 32 * t;
        wp[t] = W + (long)(n0 + n) * 1024 + kqi_w * 4;
        wsdst[t] = &Ws2[kqi_w][n ^ kqi_w][0];
    }

    int xb = tid >> 3;
    int xkq = (tid & 7) * 4;
    const float* xptr = X + xb * (2 * DD) + xkq;

    unsigned long long acc[4][4];
#pragma unroll
    for (int q = 0; q < 4; q++)
#pragma unroll
        for (int c = 0; c < 4; c++) acc[q][c] = 0ull;

    float4 xreg = *(const float4*)xptr;
    float4 wreg[4];
#pragma unroll
    for (int t = 0; t < 4; t++) wreg[t] = *(const float4*)wp[t];

    for (int k0 = 0; k0 < 1024; k0 += 32) {
        __syncthreads();
        *(float4*)&Xs[xb][xkq] = xreg;
#pragma unroll
        for (int t = 0; t < 4; t++) *(float4*)wsdst[t] = wreg[t];
        __syncthreads();
        if (k0 + 32 < 1024) {
            int kn = k0 + 32;
            xreg = *(const float4*)(xptr + kn);
#pragma unroll
            for (int t = 0; t < 4; t++) wreg[t] = *(const float4*)(wp[t] + kn);
        }
#pragma unroll
        for (int kqi = 0; kqi < 8; kqi++) {
            ulonglong2 xv[4];
#pragma unroll
            for (int q = 0; q < 4; q++)
                xv[q] = *(const ulonglong2*)&Xs[4 * w + q][kqi * 4];
#pragma unroll
            for (int c = 0; c < 4; c++) {
                ulonglong2 wv = *(const ulonglong2*)&Ws2[kqi][(tc + 32 * c) ^ kqi][0];
                FFMA2(acc[0][c], xv[0].x, wv.x); FFMA2(acc[0][c], xv[0].y, wv.y);
                FFMA2(acc[1][c], xv[1].x, wv.x); FFMA2(acc[1][c], xv[1].y, wv.y);
                FFMA2(acc[2][c], xv[2].x, wv.x); FFMA2(acc[2][c], xv[2].y, wv.y);
                FFMA2(acc[3][c], xv[3].x, wv.x); FFMA2(acc[3][c], xv[3].y, wv.y);
            }
        }
    }

    // Output: rows b = 4w+q, cols n0 + tc + 32c.
#pragma unroll
    for (int q = 0; q < 4; q++) {
        int b = 4 * w + q;
#pragma unroll
        for (int c = 0; c < 4; c++) {
            int n = n0 + tc + 32 * c;
            out[b * DD + n] = f2sum(acc[q][c]) + bias[n];
        }
    }
}

// ---------------------------------------------------------------------------
// MLP layer: out = relu(X @ W.T + b), C[32 x 512], K = 512. grid = 4 blocks.
// ---------------------------------------------------------------------------
__global__ void __launch_bounds__(256) mlp_kernel(
    const float* __restrict__ W, const float* __restrict__ bias, int stage)
{
    // Final grid cell (23,23) is on diagonal 46 (parity 0), buffer row 24.
    const float* X = (stage == 0) ? &g_dh[0][24][0][0] : &g_m1[0][0];
    float* out = (stage == 0) ? &g_m1[0][0] : &g_m2[0][0];
    int n0 = blockIdx.x * 128;

    __shared__ float Xs[32][33];
    __shared__ float Ws[128][33];
    int tid = threadIdx.x;
    int tr = tid >> 5, tc = tid & 31;

    float acc[4][4];
#pragma unroll
    for (int a = 0; a < 4; a++)
#pragma unroll
        for (int b = 0; b < 4; b++) acc[a][b] = 0.f;

    for (int k0 = 0; k0 < DD; k0 += 32) {
        {
            int b = tid >> 3;
            int kq = (tid & 7) * 4;
            float4 v = *(const float4*)(X + b * DD + k0 + kq);
            Xs[b][kq] = v.x; Xs[b][kq + 1] = v.y; Xs[b][kq + 2] = v.z; Xs[b][kq + 3] = v.w;
        }
#pragma unroll
        for (int t = 0; t < 4; t++) {
            int idx = tid + t * 256;
            int n = idx >> 3;
            int kq = (idx & 7) * 4;
            float4 w = *(const float4*)(W + (long)(n0 + n) * DD + k0 + kq);
            Ws[n][kq] = w.x; Ws[n][kq + 1] = w.y; Ws[n][kq + 2] = w.z; Ws[n][kq + 3] = w.w;
        }
        __syncthreads();
#pragma unroll
        for (int kk = 0; kk < 32; kk++) {
            float xv[4], wv[4];
#pragma unroll
            for (int rr = 0; rr < 4; rr++) xv[rr] = Xs[tr + 8 * rr][kk];
#pragma unroll
            for (int cc = 0; cc < 4; cc++) wv[cc] = Ws[cc * 32 + tc][kk];
#pragma unroll
            for (int rr = 0; rr < 4; rr++)
#pragma unroll
                for (int cc = 0; cc < 4; cc++)
                    acc[rr][cc] = fmaf(xv[rr], wv[cc], acc[rr][cc]);
        }
        __syncthreads();
    }

#pragma unroll
    for (int rr = 0; rr < 4; rr++) {
        int b = tr + 8 * rr;
#pragma unroll
        for (int cc = 0; cc < 4; cc++) {
            int n = n0 + cc * 32 + tc;
            out[b * DD + n] = fmaxf(acc[rr][cc] + bias[n], 0.f);
        }
    }
}

// ---------------------------------------------------------------------------
// Final: logits = g_m2 @ W3.T + b3 ; softmax over 3 classes. out [32,3] f32.
// ---------------------------------------------------------------------------
__global__ void __launch_bounds__(128) final_kernel(
    const float* __restrict__ W3, const float* __restrict__ b3, float* __restrict__ out)
{
    __shared__ float logits[32][3];
    int t = threadIdx.x;
    if (t < 96) {
        int b = t / 3, c = t % 3;
        float s = b3[c];
        for (int k = 0; k < DD; k++) s += g_m2[b][k] * W3[c * DD + k];
        logits[b][c] = s;
    }
    __syncthreads();
    if (t < 96) {
        int b = t / 3, c = t % 3;
        float mx = fmaxf(logits[b][0], fmaxf(logits[b][1], logits[b][2]));
        float e0 = expf(logits[b][0] - mx);
        float e1 = expf(logits[b][1] - mx);
        float e2 = expf(logits[b][2] - mx);
        out[b * 3 + c] = expf(logits[b][c] - mx) / (e0 + e1 + e2);
    }
}

// ---------------------------------------------------------------------------
extern "C" void kernel_launch(void* const* d_in, const int* in_sizes, int n_in,
                              void* d_out, int out_size)
{
    const int*   premise    = (const int*)d_in[0];
    const int*   hypothesis = (const int*)d_in[1];
    const float* emb        = (const float*)d_in[2];
    const float* W_ih       = (const float*)d_in[3];
    const float* W_hh       = (const float*)d_in[4];
    const float* b_ih       = (const float*)d_in[5];
    const float* b_hh       = (const float*)d_in[6];
    const float* W_ch       = (const float*)d_in[7];
    const float* b_ch       = (const float*)d_in[8];
    const float* W_cc       = (const float*)d_in[9];
    const float* b_cc       = (const float*)d_in[10];
    const float* W1         = (const float*)d_in[11];
    const float* b1         = (const float*)d_in[12];
    const float* W2         = (const float*)d_in[13];
    const float* b2         = (const float*)d_in[14];
    const float* W3         = (const float*)d_in[15];
    const float* b3         = (const float*)d_in[16];
    float* out = (float*)d_out;

    prologue_kernel<<<dim3(24, 32, 2), 256>>>(premise, hypothesis, emb, W_ih, b_ih, b_hh);

    for (int d = 0; d <= PP + HHN - 2; d++) {
        int i_lo = d - (HHN - 1); if (i_lo < 0) i_lo = 0;
        int i_hi = d < (PP - 1) ? d : (PP - 1);
        int nc = i_hi - i_lo + 1;
        int parity = d & 1;
        gates_kernel<<<dim3(nc, 32), 256>>>(W_hh, d, i_lo, parity);
        condense_kernel<<<dim3(nc, 8), 256>>>(W_ch, b_ch, W_cc, b_cc, d, i_lo, parity);
    }

    mlp_kernel<<<4, 256>>>(W1, b1, 0);
    mlp_kernel<<<4, 256>>>(W2, b2, 1);
    final_kernel<<<1, 128>>>(W3, b3, out);
}